// round 8
// baseline (speedup 1.0000x reference)
#include <cuda_runtime.h>
#include <stdint.h>

// RadialTokenizer — coalesced stream + smem-staged gather.
// Per (b,c) image: quantize floor((x*0.5+0.5)*255) -> [127,254] (128 bins);
// 16 radial rings: mean/std/median from exact per-ring 128-bin histograms.
// Block = one (b,c) image. Image streamed in 16-row stripes via 16B cp.async
// (coalesced, double-buffered). Warp w owns rings (w, 15-w); gathers its
// rings' pixels from the smem stripe (ring-major offsets -> span-contiguous
// LDS). Per-ring per-lane byte histograms (conflict-free, single-warp
// ownership, no atomics).

#define HH 256
#define WW 256
#define NR 16
#define MAXPIX 53248

__device__ __align__(128) uint16_t g_off[MAXPIX];
__device__ int g_ringbase[NR + 1];   // starts (multiples of 64 entries)
__device__ int g_ringlen[NR];        // true pixel counts
__device__ int g_rowcnt[HH * NR];
__device__ int g_rowstart[HH * NR];

// ring i <=> 64*i^2 < d2 <= 64*(i+1)^2 ; center pixel excluded.
__device__ __forceinline__ int ring_of(int x, int y) {
    int dx = x - 128, dy = y - 128;
    int d2 = dx * dx + dy * dy;
    if (d2 == 0 || d2 > 16384) return -1;
    int i = (int)(__fmul_rn(sqrtf((float)d2), 0.125f) + 0.999f) - 1;
    if (i < 0) i = 0;
    while (i > 0 && 64 * i * i >= d2) i--;
    while (d2 > 64 * (i + 1) * (i + 1)) i++;
    return i;
}

// ---------------- init kernels (deterministic, every launch) ----------------

__global__ void k_count() {
    __shared__ int cnt[NR];
    int x = threadIdx.x, y = blockIdx.x;
    int lane = x & 31;
    if (x < NR) cnt[x] = 0;
    __syncthreads();
    int r = ring_of(x, y);
    unsigned m = __match_any_sync(0xffffffffu, r);
    if (r >= 0 && (m & ((1u << lane) - 1)) == 0)
        atomicAdd(&cnt[r], __popc(m));
    __syncthreads();
    if (x < NR) g_rowcnt[y * NR + x] = cnt[x];
}

__global__ void k_prefix() {
    int t = threadIdx.x;
    __shared__ int tot[NR];
    __shared__ int base[NR];
    if (t < NR) {
        int s = 0;
        for (int y = 0; y < HH; y++) s += g_rowcnt[y * NR + t];
        tot[t] = s;
    }
    __syncthreads();
    if (t == 0) {
        int run = 0;
        for (int r = 0; r < NR; r++) {
            base[r] = run;
            g_ringbase[r] = run;
            g_ringlen[r] = tot[r];
            run += (tot[r] + 63) & ~63;
        }
        g_ringbase[NR] = run;
    }
    __syncthreads();
    if (t < NR) {
        int run = base[t];
        for (int y = 0; y < HH; y++) {
            g_rowstart[y * NR + t] = run;
            run += g_rowcnt[y * NR + t];
        }
    }
}

__global__ void k_scatter() {
    __shared__ int wcnt[8][NR];
    __shared__ int wbase[8][NR];
    int x = threadIdx.x, y = blockIdx.x;
    int lane = x & 31, w = x >> 5;
    int r = ring_of(x, y);
    unsigned m = __match_any_sync(0xffffffffu, r);
    int rank = __popc(m & ((1u << lane) - 1));
    if (x < 8 * NR) ((int*)wcnt)[x] = 0;
    __syncthreads();
    if (r >= 0 && rank == 0) wcnt[w][r] = __popc(m);
    __syncthreads();
    if (x < NR) {
        int run = 0;
        #pragma unroll
        for (int ww = 0; ww < 8; ww++) { wbase[ww][x] = run; run += wcnt[ww][x]; }
    }
    __syncthreads();
    if (r >= 0)
        g_off[g_rowstart[y * NR + r] + wbase[w][r] + rank] = (uint16_t)(y * WW + x);
}

// ---------------- main kernel ----------------
// Dynamic smem: float stage[2][4096] (32KB) + uint8 hist[16][4096] (64KB)
// = 96KB -> 2 blocks/SM. Grid 768 (one block per (b,c)).
// Hist byte addr = ((bin<<5)&0xF80) | (lane<<2) | (bin&3)  -> bank == lane.

__global__ void __launch_bounds__(256) k_main(const float* __restrict__ img,
                                              float* __restrict__ out) {
    extern __shared__ __align__(16) uint8_t smem[];
    float*   stage = (float*)smem;          // [2][4096]
    uint8_t* hist  = smem + 32768;          // [16][4096]

    const int tid  = threadIdx.x;
    const int lane = tid & 31;
    const int w    = tid >> 5;
    const int bc   = blockIdx.x;
    const float* __restrict__ ip = img + (size_t)bc * (HH * WW);

    // zero all 16 ring histograms (64KB)
    {
        uint4* hz = (uint4*)hist;
        uint4 z; z.x = z.y = z.z = z.w = 0u;
        #pragma unroll
        for (int k = 0; k < 16; k++) hz[tid + 256 * k] = z;
    }

    const uint32_t stg = (uint32_t)__cvta_generic_to_shared(stage);

    // prefetch stripe 0 (16 rows = 4096 floats), coalesced 16B cp.async
    {
        const float* src = ip;
        #pragma unroll
        for (int k = 0; k < 4; k++) {
            uint32_t d = stg + (uint32_t)(tid + 256 * k) * 16u;
            asm volatile("cp.async.cg.shared.global [%0], [%1], 16;"
                         :: "r"(d), "l"(src + (tid + 256 * k) * 4) : "memory");
        }
        asm volatile("cp.async.commit_group;" ::: "memory");
    }

    const int rA = w, rB = 15 - w;
    uint8_t* hA = hist + (rA << 12);
    uint8_t* hB = hist + (rB << 12);
    const int hb_lane = lane << 2;

    for (int t = 0; t < 16; t++) {
        if (t < 15) {
            const float* src = ip + (t + 1) * 4096;
            uint32_t dbase = stg + (uint32_t)(((t + 1) & 1) * 16384);
            #pragma unroll
            for (int k = 0; k < 4; k++) {
                uint32_t d = dbase + (uint32_t)(tid + 256 * k) * 16u;
                asm volatile("cp.async.cg.shared.global [%0], [%1], 16;"
                             :: "r"(d), "l"(src + (tid + 256 * k) * 4) : "memory");
            }
            asm volatile("cp.async.commit_group;" ::: "memory");
            asm volatile("cp.async.wait_group 1;" ::: "memory");
        } else {
            asm volatile("cp.async.wait_group 0;" ::: "memory");
        }
        __syncthreads();    // stripe t visible to all warps

        const float* __restrict__ buf = stage + (t & 1) * 4096;
        const int y0 = t * 16, y1 = y0 + 16;

        #pragma unroll
        for (int q = 0; q < 2; q++) {
            const int r = q ? rB : rA;
            uint8_t* h = q ? hB : hA;
            int s = g_rowstart[y0 * NR + r];
            int e = (y1 == HH) ? (g_ringbase[r] + g_ringlen[r])
                               : g_rowstart[y1 * NR + r];
            #pragma unroll 4
            for (int i = s + lane; i < e; i += 32) {
                int off = g_off[i];
                float v = buf[off & 4095];
                // bit-identical to ref: fma(x,0.5,0.5) (exact mul, single
                // rounding) == (x*0.5)+0.5; then unfused *255; floor.
                float tq = __fmul_rn(__fmaf_rn(v, 0.5f, 0.5f), 255.0f);
                int bin = __float2int_rd(tq) - 127;
                h[((bin << 5) & 0xF80) | hb_lane | (bin & 3)] += 1;
            }
        }
        __syncthreads();    // all reads of buf done before it is overwritten
    }

    // ---- epilogue: warp w reduces rings rA, rB ----
    const int b = bc / 3, c = bc - b * 3;
    #pragma unroll
    for (int q = 0; q < 2; q++) {
        const int ring = q ? rB : rA;
        const uint8_t* h = q ? hB : hA;
        const int n = g_ringlen[ring];

        const uint32_t* hw = (const uint32_t*)h;
        uint32_t a02 = 0, a13 = 0;
        #pragma unroll
        for (int jj = 0; jj < 32; jj++) {
            int j = (jj + lane) & 31;
            uint32_t vv = hw[lane * 32 + j];
            a02 += vv & 0x00FF00FFu;
            a13 += (vv >> 8) & 0x00FF00FFu;
        }
        int h0 = (int)(a02 & 0xFFFFu), h2 = (int)(a02 >> 16);
        int h1 = (int)(a13 & 0xFFFFu), h3 = (int)(a13 >> 16);

        const int b0 = lane * 4;
        int sl  = h0 + h1 + h2 + h3;
        int sb  = h0 * b0 + h1 * (b0 + 1) + h2 * (b0 + 2) + h3 * (b0 + 3);
        int sb2 = h0 * b0 * b0 + h1 * (b0 + 1) * (b0 + 1)
                + h2 * (b0 + 2) * (b0 + 2) + h3 * (b0 + 3) * (b0 + 3);

        int sumb  = __reduce_add_sync(0xffffffffu, sb);
        int sumb2 = __reduce_add_sync(0xffffffffu, sb2);

        int sc = sl;
        #pragma unroll
        for (int d = 1; d < 32; d <<= 1) {
            int t2 = __shfl_up_sync(0xffffffffu, sc, d);
            if (lane >= d) sc += t2;
        }
        int cb = sc - sl;

        int k1 = (n - 1) >> 1, k2 = n >> 1;
        int c1 = 1 << 30, c2 = 1 << 30;
        {
            int t1 = k1 + 1;
            if (cb < t1 && t1 <= sc) {
                if      (cb + h0 >= t1)           c1 = b0;
                else if (cb + h0 + h1 >= t1)      c1 = b0 + 1;
                else if (cb + h0 + h1 + h2 >= t1) c1 = b0 + 2;
                else                              c1 = b0 + 3;
            }
            int t2r = k2 + 1;
            if (cb < t2r && t2r <= sc) {
                if      (cb + h0 >= t2r)           c2 = b0;
                else if (cb + h0 + h1 >= t2r)      c2 = b0 + 1;
                else if (cb + h0 + h1 + h2 >= t2r) c2 = b0 + 2;
                else                               c2 = b0 + 3;
            }
        }
        int m1 = __reduce_min_sync(0xffffffffu, c1);
        int m2 = __reduce_min_sync(0xffffffffu, c2);

        if (lane == 0) {
            double dn = (double)n;
            double mb = (double)sumb / dn;
            double mean = 127.0 + mb;
            double var = (double)sumb2 / dn - mb * mb;
            double sd = sqrt(var > 0.0 ? var : 0.0);
            double med = 127.0 + 0.5 * (double)(m1 + m2);
            int o = b * (NR * 9) + ring * 9 + c;
            out[o]     = (float)mean;
            out[o + 3] = (float)sd;
            out[o + 6] = (float)med;
        }
    }
}

extern "C" void kernel_launch(void* const* d_in, const int* in_sizes, int n_in,
                              void* d_out, int out_size) {
    const float* img = (const float*)d_in[0];
    float* out = (float*)d_out;

    static int attr_set = 0;
    if (!attr_set) {
        cudaFuncSetAttribute(k_main, cudaFuncAttributeMaxDynamicSharedMemorySize,
                             98304);
        attr_set = 1;
    }

    k_count<<<HH, WW>>>();
    k_prefix<<<1, 32>>>();
    k_scatter<<<HH, WW>>>();

    k_main<<<768, 256, 98304>>>(img, out);
}

// round 9
// speedup vs baseline: 3.1162x; 3.1162x over previous
#include <cuda_runtime.h>
#include <stdint.h>

// RadialTokenizer — fused quantize-to-smem + in-smem ring gather.
// Per (b,c) image: bin = floor((x*0.5+0.5)*255)-127 in [0,127].
// Phase A: stream image coalesced (float4), write bin bytes to 64KB smem.
// Phase B: warp w gathers rings (w, 15-w) from smem bins via offset lists,
// builds per-lane byte histograms (bank==lane, conflict-free, no atomics),
// then mean/std/median from the histogram. One barrier per block.
// Offset lists rebuilt each launch by 2 tiny kernels (atomic cursor; order
// within a ring is irrelevant for histograms).

#define HH 256
#define WW 256
#define NR 16
#define RSTRIDE 8192   // max ring population ~6233 < 8192

__device__ int g_cnt[NR];                                   // ring counts
__device__ __align__(128) uint16_t g_off[NR * RSTRIDE];     // ring px lists

// ring i <=> 64*i^2 < d2 <= 64*(i+1)^2 ; center pixel excluded.
__device__ __forceinline__ int ring_of(int x, int y) {
    int dx = x - 128, dy = y - 128;
    int d2 = dx * dx + dy * dy;
    if (d2 == 0 || d2 > 16384) return -1;
    int i = (int)(__fmul_rn(sqrtf((float)d2), 0.125f) + 0.999f) - 1;
    if (i < 0) i = 0;
    while (i > 0 && 64 * i * i >= d2) i--;
    while (d2 > 64 * (i + 1) * (i + 1)) i++;
    return i;
}

__global__ void k_zero() {
    if (threadIdx.x < NR) g_cnt[threadIdx.x] = 0;
}

__global__ void k_build() {
    int px = blockIdx.x * 256 + threadIdx.x;
    int x = px & 255, y = px >> 8;
    int r = ring_of(x, y);
    if (r >= 0) {
        int pos = atomicAdd(&g_cnt[r], 1);
        g_off[r * RSTRIDE + pos] = (uint16_t)px;
    }
}

// ---------------- main kernel ----------------
// Grid 768 (block = one (b,c)), 256 threads, 96KB dyn smem -> 2 blocks/SM.
// smem: bins u8[65536] (quantized image) + hist u8[8][4096] (per-warp).
// Hist byte addr = ((bin<<5)&0xF80) | (lane<<2) | (bin&3)  -> bank == lane.

__global__ void __launch_bounds__(256, 2) k_main(const float* __restrict__ img,
                                                 float* __restrict__ out) {
    extern __shared__ __align__(16) uint8_t smem[];
    uint8_t* bins = smem;              // 64KB
    uint8_t* hist = smem + 65536;      // 32KB

    const int tid  = threadIdx.x;
    const int lane = tid & 31;
    const int w    = tid >> 5;
    const int bc   = blockIdx.x;
    const float* __restrict__ ip = img + (size_t)bc * (HH * WW);

    // zero hists (32KB) while loads start
    {
        uint4* hz = (uint4*)hist;
        uint4 z; z.x = z.y = z.z = z.w = 0u;
        #pragma unroll
        for (int k = 0; k < 8; k++) hz[tid + 256 * k] = z;
    }

    // ---- Phase A: coalesced stream, quantize, pack 4 bins -> u32 ----
    const float4* __restrict__ ipv = (const float4*)ip;
    uint32_t* binw = (uint32_t*)bins;
    #pragma unroll 8
    for (int i = 0; i < 64; i++) {
        int idx = i * 256 + tid;
        float4 q = __ldcs(&ipv[idx]);
        // bit-identical to ref: fma(x,0.5,0.5) (exact mul => single rounding
        // equals (x*0.5)+0.5), then unfused *255, then floor.
        int b0 = __float2int_rd(__fmul_rn(__fmaf_rn(q.x, 0.5f, 0.5f), 255.0f)) - 127;
        int b1 = __float2int_rd(__fmul_rn(__fmaf_rn(q.y, 0.5f, 0.5f), 255.0f)) - 127;
        int b2 = __float2int_rd(__fmul_rn(__fmaf_rn(q.z, 0.5f, 0.5f), 255.0f)) - 127;
        int b3 = __float2int_rd(__fmul_rn(__fmaf_rn(q.w, 0.5f, 0.5f), 255.0f)) - 127;
        binw[idx] = (uint32_t)b0 | ((uint32_t)b1 << 8)
                  | ((uint32_t)b2 << 16) | ((uint32_t)b3 << 24);
    }
    __syncthreads();

    // ---- Phase B: warp w -> rings (w, 15-w), gather bins from smem ----
    uint8_t* h = hist + (w << 12);
    const int hb_lane = lane << 2;
    const int b = bc / 3, c = bc - b * 3;
    const int bin0 = bins[0];          // sentinel pixel's bin

    #pragma unroll
    for (int q = 0; q < 2; q++) {
        const int ring = q ? (15 - w) : w;
        const int n = g_cnt[ring];
        const int nsteps = (n + 63) >> 6;
        const int pad = (nsteps << 6) - n;   // sentinel entries (offset 0)
        const uint32_t* __restrict__ o32 =
            (const uint32_t*)(g_off + ring * RSTRIDE);

        #pragma unroll 4
        for (int s = 0; s < nsteps; s++) {
            uint32_t ow = o32[(s << 5) + lane];
            int v0 = bins[ow & 0xFFFFu];
            int v1 = bins[ow >> 16];
            h[((v0 << 5) & 0xF80) | hb_lane | (v0 & 3)] += 1;
            h[((v1 << 5) & 0xF80) | hb_lane | (v1 & 3)] += 1;
        }
        __syncwarp();

        // reduce: lane l owns bins 4l..4l+3; sum byte counters of 32 lanes.
        const uint32_t* hw = (const uint32_t*)h;
        uint32_t a02 = 0, a13 = 0;
        #pragma unroll
        for (int jj = 0; jj < 32; jj++) {
            int j = (jj + lane) & 31;
            uint32_t vv = hw[lane * 32 + j];
            a02 += vv & 0x00FF00FFu;
            a13 += (vv >> 8) & 0x00FF00FFu;
        }
        int h0 = (int)(a02 & 0xFFFFu), h2 = (int)(a02 >> 16);
        int h1 = (int)(a13 & 0xFFFFu), h3 = (int)(a13 >> 16);

        // subtract sentinel-pad counts from bin0
        if ((bin0 >> 2) == lane) {
            int qq = bin0 & 3;
            if (qq == 0) h0 -= pad;
            else if (qq == 1) h1 -= pad;
            else if (qq == 2) h2 -= pad;
            else h3 -= pad;
        }

        const int b0r = lane * 4;
        int sl  = h0 + h1 + h2 + h3;
        int sb  = h0 * b0r + h1 * (b0r + 1) + h2 * (b0r + 2) + h3 * (b0r + 3);
        int sb2 = h0 * b0r * b0r + h1 * (b0r + 1) * (b0r + 1)
                + h2 * (b0r + 2) * (b0r + 2) + h3 * (b0r + 3) * (b0r + 3);

        int sumb  = __reduce_add_sync(0xffffffffu, sb);
        int sumb2 = __reduce_add_sync(0xffffffffu, sb2);

        int sc = sl;
        #pragma unroll
        for (int d = 1; d < 32; d <<= 1) {
            int t2 = __shfl_up_sync(0xffffffffu, sc, d);
            if (lane >= d) sc += t2;
        }
        int cb = sc - sl;

        int k1 = (n - 1) >> 1, k2 = n >> 1;
        int c1 = 1 << 30, c2 = 1 << 30;
        {
            int t1 = k1 + 1;
            if (cb < t1 && t1 <= sc) {
                if      (cb + h0 >= t1)           c1 = b0r;
                else if (cb + h0 + h1 >= t1)      c1 = b0r + 1;
                else if (cb + h0 + h1 + h2 >= t1) c1 = b0r + 2;
                else                              c1 = b0r + 3;
            }
            int t2r = k2 + 1;
            if (cb < t2r && t2r <= sc) {
                if      (cb + h0 >= t2r)           c2 = b0r;
                else if (cb + h0 + h1 >= t2r)      c2 = b0r + 1;
                else if (cb + h0 + h1 + h2 >= t2r) c2 = b0r + 2;
                else                               c2 = b0r + 3;
            }
        }
        int m1 = __reduce_min_sync(0xffffffffu, c1);
        int m2 = __reduce_min_sync(0xffffffffu, c2);

        if (lane == 0) {
            double dn = (double)n;
            double mb = (double)sumb / dn;
            double mean = 127.0 + mb;
            double var = (double)sumb2 / dn - mb * mb;
            double sd = sqrt(var > 0.0 ? var : 0.0);
            double med = 127.0 + 0.5 * (double)(m1 + m2);
            int o = b * (NR * 9) + ring * 9 + c;
            out[o]     = (float)mean;
            out[o + 3] = (float)sd;
            out[o + 6] = (float)med;
        }
        __syncwarp();

        // rezero hist for the second ring
        if (q == 0) {
            uint4* hz = (uint4*)h;
            uint4 z; z.x = z.y = z.z = z.w = 0u;
            #pragma unroll
            for (int k = 0; k < 8; k++) hz[k * 32 + lane] = z;
            __syncwarp();
        }
    }
}

extern "C" void kernel_launch(void* const* d_in, const int* in_sizes, int n_in,
                              void* d_out, int out_size) {
    const float* img = (const float*)d_in[0];
    float* out = (float*)d_out;

    static int attr_set = 0;
    if (!attr_set) {
        cudaFuncSetAttribute(k_main, cudaFuncAttributeMaxDynamicSharedMemorySize,
                             98304);
        attr_set = 1;
    }

    k_zero<<<1, 32>>>();
    k_build<<<HH, WW>>>();
    k_main<<<768, 256, 98304>>>(img, out);
}